// round 2
// baseline (speedup 1.0000x reference)
#include <cuda_runtime.h>

#define NH 192            // nH = nW = 193 - 2 + 1
#define HG 193            // grid H/W
#define MD 64             // vec dim m
#define B_TOTAL (NH * NH) // 36864

// Scratch (allocation-free rule: __device__ globals)
__device__ float g_cosT[NH * MD * MD];   // cos(2*pi*k / T[i,j]),  3 MB
__device__ float g_x[B_TOTAL * MD];      // x = win_avg(grid) @ M^T, 9.4 MB

// ---------------------------------------------------------------------------
// Kernel 1: cos table. cosT[k,i,j] = cosf(2*pi*k / (i*64 + j + 2))
// ---------------------------------------------------------------------------
__global__ void build_cos_table() {
    int idx = blockIdx.x * blockDim.x + threadIdx.x;
    if (idx >= NH * MD * MD) return;
    int k = idx >> 12;
    int r = idx & 4095;
    int i = r >> 6;
    int j = r & 63;
    float period = (float)(i * MD + j + 2);
    float arg = 6.2831853071795864769f * (float)k / period;  // fp32, same as reference
    g_cosT[idx] = cosf(arg);
}

// ---------------------------------------------------------------------------
// Kernel 2: x[b, j] = sum_l wavg[b, l] * M[j, l]
//   wavg[b, l] = 0.25 * (grid[k1,k2,l] + grid[k1,k2+1,l]
//                       + grid[k1+1,k2,l] + grid[k1+1,k2+1,l])
// Grid: (6 k2-chunks of 32, 192 k1). 256 threads = (q in 0..3) x (j in 0..63).
// Each thread keeps M[j, :] in 64 registers.
// ---------------------------------------------------------------------------
__global__ void __launch_bounds__(256) compute_x(const float* __restrict__ grid,
                                                 const float* __restrict__ Mw) {
    __shared__ float Msm[64][65];            // padded: conflict-free row reads
    __shared__ __align__(16) float wv[4][64];

    int t  = threadIdx.x;
    int q  = t >> 6;
    int jl = t & 63;

    // stage M coalesced, then pull row jl into registers (pad 65 -> no conflicts)
    for (int e = t; e < 4096; e += 256) Msm[e >> 6][e & 63] = Mw[e];
    __syncthreads();
    float Mreg[64];
#pragma unroll
    for (int l = 0; l < 64; l++) Mreg[l] = Msm[jl][l];

    int k1     = blockIdx.y;
    int k2base = blockIdx.x * 32;

    for (int g = 0; g < 8; g++) {
        __syncthreads();  // protect wv reuse
        int k2 = k2base + g * 4 + q;
        const float* g00 = grid + ((k1 * HG + k2) * MD);
        wv[q][jl] = 0.25f * (g00[jl] + g00[MD + jl] +
                             g00[HG * MD + jl] + g00[HG * MD + MD + jl]);
        __syncthreads();

        float acc = 0.f;
        const float4* wv4 = reinterpret_cast<const float4*>(&wv[q][0]);  // broadcast
#pragma unroll
        for (int l4 = 0; l4 < 16; l4++) {
            float4 w = wv4[l4];
            acc = fmaf(Mreg[4 * l4 + 0], w.x, acc);
            acc = fmaf(Mreg[4 * l4 + 1], w.y, acc);
            acc = fmaf(Mreg[4 * l4 + 2], w.z, acc);
            acc = fmaf(Mreg[4 * l4 + 3], w.w, acc);
        }
        g_x[(k1 * NH + k2) * MD + jl] = acc;
    }
}

// ---------------------------------------------------------------------------
// Kernel 3: Nk[b, i] = sum_j x[b,j] * (P[i,j] * cosT[k1,i,j]) * cosT[k2,i,j]
// Grid: (6 k2-chunks of 32, 48 k1-tiles of 4). 256 threads = (k1sub 0..3) x (i 0..63).
// Per thread: C1reg[j] = P[i,j] * cosT[k1,i,j] held in 64 registers across all k2.
// Per k2 step: cos slice staged in smem (row pad 68 -> conflict-free float4 reads),
// x rows broadcast from smem.
// ---------------------------------------------------------------------------
__global__ void __launch_bounds__(256) main_kernel(const float* __restrict__ P,
                                                   float* __restrict__ out) {
    __shared__ __align__(16) float c2buf[64][68];  // 272 B rows: 16B-aligned, bank-shift 4
    __shared__ float Ps[64][65];
    __shared__ __align__(16) float xs[4][64];

    int t     = threadIdx.x;
    int k1sub = t >> 6;
    int i     = t & 63;
    int k1    = blockIdx.y * 4 + k1sub;

    // stage P coalesced once
    for (int e = t; e < 4096; e += 256) Ps[e >> 6][e & 63] = P[e];

    // build C1reg: for each of the 4 k1 slices, stage cosT[k1] and let the
    // owning quarter of threads read its row
    float C1reg[64];
    for (int s = 0; s < 4; s++) {
        __syncthreads();
        const float4* src = reinterpret_cast<const float4*>(
            g_cosT + (blockIdx.y * 4 + s) * 4096);
        for (int e4 = t; e4 < 1024; e4 += 256) {
            float4 v = src[e4];
            int e = e4 * 4;
            *reinterpret_cast<float4*>(&c2buf[e >> 6][e & 63]) = v;
        }
        __syncthreads();
        if (k1sub == s) {
#pragma unroll
            for (int j = 0; j < 64; j++) C1reg[j] = c2buf[i][j] * Ps[i][j];
        }
    }

    int k2base = blockIdx.x * 32;

    for (int kk = 0; kk < 32; kk++) {
        int k2 = k2base + kk;
        __syncthreads();  // protect c2buf / xs reuse

        // stage cosT[k2] slice (16 KB) coalesced
        const float4* src = reinterpret_cast<const float4*>(g_cosT + k2 * 4096);
        for (int e4 = t; e4 < 1024; e4 += 256) {
            float4 v = src[e4];
            int e = e4 * 4;
            *reinterpret_cast<float4*>(&c2buf[e >> 6][e & 63]) = v;
        }
        // stage the 4 x rows (one per k1sub)
        {
            int s = t >> 6, j = t & 63;
            xs[s][j] = g_x[((blockIdx.y * 4 + s) * NH + k2) * MD + j];
        }
        __syncthreads();

        float acc = 0.f;
        const float4* c2r = reinterpret_cast<const float4*>(&c2buf[i][0]);
        const float4* xr  = reinterpret_cast<const float4*>(&xs[k1sub][0]);  // broadcast
#pragma unroll
        for (int q = 0; q < 16; q++) {
            float4 c  = c2r[q];
            float4 xv = xr[q];
            acc = fmaf(C1reg[4 * q + 0] * c.x, xv.x, acc);
            acc = fmaf(C1reg[4 * q + 1] * c.y, xv.y, acc);
            acc = fmaf(C1reg[4 * q + 2] * c.z, xv.z, acc);
            acc = fmaf(C1reg[4 * q + 3] * c.w, xv.w, acc);
        }
        out[(k1 * NH + k2) * MD + i] = acc;
    }
}

// ---------------------------------------------------------------------------
// Launch: inputs in metadata order: grid [193,193,64], M_weight [64,64], P [64,64]
// ---------------------------------------------------------------------------
extern "C" void kernel_launch(void* const* d_in, const int* in_sizes, int n_in,
                              void* d_out, int out_size) {
    const float* grid = (const float*)d_in[0];
    const float* Mw   = (const float*)d_in[1];
    const float* P    = (const float*)d_in[2];
    float* out        = (float*)d_out;

    build_cos_table<<<(NH * MD * MD + 255) / 256, 256>>>();
    compute_x<<<dim3(6, NH), 256>>>(grid, Mw);
    main_kernel<<<dim3(6, NH / 4), 256>>>(P, out);
}

// round 6
// speedup vs baseline: 1.1055x; 1.1055x over previous
#include <cuda_runtime.h>

#define NH 192            // nH = nW = 193 - 2 + 1
#define HG 193            // grid H/W
#define MD 64             // vec dim m
#define PITCH 68          // padded row (floats): conflict-free float4 LDS (68 % 32 == 4)

// Scratch (allocation-free rule: __device__ globals)
__device__ float g_cosT[NH * MD * MD];   // cos(2*pi*k / T[i,j]),  3 MB
__device__ float g_x[NH * NH * MD];      // x = win_avg(grid) @ M^T, 9.4 MB

// ---------------------------------------------------------------------------
// Kernel 1: cos table. cosT[k,i,j] = cosf(2*pi*k / (i*64 + j + 2))
// ---------------------------------------------------------------------------
__global__ void build_cos_table() {
    int idx = blockIdx.x * blockDim.x + threadIdx.x;
    if (idx >= NH * MD * MD) return;
    int k = idx >> 12;
    int r = idx & 4095;
    int i = r >> 6;
    int j = r & 63;
    float period = (float)(i * MD + j + 2);
    float arg = 6.2831853071795864769f * (float)k / period;  // fp32, matches reference
    g_cosT[idx] = cosf(arg);
}

// ---------------------------------------------------------------------------
// Kernel 2: x[b, j] = sum_l wavg[b, l] * M[j, l]   (exact R2 version — proven)
// ---------------------------------------------------------------------------
__global__ void __launch_bounds__(256) compute_x(const float* __restrict__ grid,
                                                 const float* __restrict__ Mw) {
    __shared__ float Msm[64][65];
    __shared__ __align__(16) float wv[4][64];

    int t  = threadIdx.x;
    int q  = t >> 6;
    int jl = t & 63;

    for (int e = t; e < 4096; e += 256) Msm[e >> 6][e & 63] = Mw[e];
    __syncthreads();
    float Mreg[64];
#pragma unroll
    for (int l = 0; l < 64; l++) Mreg[l] = Msm[jl][l];

    int k1     = blockIdx.y;
    int k2base = blockIdx.x * 32;

    for (int g = 0; g < 8; g++) {
        __syncthreads();  // protect wv reuse
        int k2 = k2base + g * 4 + q;
        const float* g00 = grid + ((k1 * HG + k2) * MD);
        wv[q][jl] = 0.25f * (g00[jl] + g00[MD + jl] +
                             g00[HG * MD + jl] + g00[HG * MD + MD + jl]);
        __syncthreads();

        float acc = 0.f;
        const float4* wv4 = reinterpret_cast<const float4*>(&wv[q][0]);
#pragma unroll
        for (int l4 = 0; l4 < 16; l4++) {
            float4 w = wv4[l4];
            acc = fmaf(Mreg[4 * l4 + 0], w.x, acc);
            acc = fmaf(Mreg[4 * l4 + 1], w.y, acc);
            acc = fmaf(Mreg[4 * l4 + 2], w.z, acc);
            acc = fmaf(Mreg[4 * l4 + 3], w.w, acc);
        }
        g_x[(k1 * NH + k2) * MD + jl] = acc;
    }
}

// ---------------------------------------------------------------------------
// Kernel 3: Nk[b,i] = sum_j x[b,j] * (P[i,j]*cosT[k1,i,j]) * cosT[k2,i,j]
//
// 512 threads = (k1sub 0..7) x (i 0..63); ONE output per thread per k2
// (verbatim R2 per-thread structure, just 8 k1 rows per CTA instead of 4).
// Grid (6 k2-chunks of 32, 24 k1-tiles of 8) = 144 CTAs = one wave.
// C1reg[j] = P[i,j] * cosT[k1,i,j] in 64 registers, reused across 32 k2 steps.
// Staging: R2's proven two-barrier in-loop LDG->STS. No prefetch, no f32x2.
// ---------------------------------------------------------------------------
__global__ void __launch_bounds__(512, 1) main_kernel(const float* __restrict__ P,
                                                      float* __restrict__ out) {
    __shared__ __align__(16) float cbuf[64 * PITCH];   // 17.4 KB cos slice (swing buffer)
    __shared__ float Ps[64][65];
    __shared__ __align__(16) float xsm[8 * 64];        // 8 x rows for current k2

    int t      = threadIdx.x;
    int i      = t & 63;
    int k1sub  = t >> 6;                // 0..7
    int k1base = blockIdx.y * 8;
    int k1     = k1base + k1sub;

    // stage P once (coalesced)
    for (int e = t; e < 4096; e += 512) Ps[e >> 6][e & 63] = P[e];

    // --- build C1reg: stage each of the 8 k1 cos slices; owner eighth reads ---
    float C1reg[64];
    for (int s = 0; s < 8; s++) {
        __syncthreads();
        const float4* src = reinterpret_cast<const float4*>(g_cosT + (k1base + s) * 4096);
        for (int e4 = t; e4 < 1024; e4 += 512) {
            float4 v = src[e4];
            int e = e4 * 4;
            *reinterpret_cast<float4*>(&cbuf[(e >> 6) * PITCH + (e & 63)]) = v;
        }
        __syncthreads();
        if (k1sub == s) {
#pragma unroll
            for (int j = 0; j < 64; j++) C1reg[j] = cbuf[i * PITCH + j] * Ps[i][j];
        }
    }

    int k2base = blockIdx.x * 32;

    for (int kk = 0; kk < 32; kk++) {
        int k2 = k2base + kk;
        __syncthreads();   // readers of previous slice (or C1 build) are done

        // stage cosT[k2] slice (16 KB) coalesced: 2 float4 per thread
        const float4* src = reinterpret_cast<const float4*>(g_cosT + k2 * 4096);
        for (int e4 = t; e4 < 1024; e4 += 512) {
            float4 v = src[e4];
            int e = e4 * 4;
            *reinterpret_cast<float4*>(&cbuf[(e >> 6) * PITCH + (e & 63)]) = v;
        }
        // stage the 8 x rows (one float per thread)
        xsm[(t >> 6) * 64 + (t & 63)] =
            g_x[((k1base + (t >> 6)) * NH + k2) * MD + (t & 63)];
        __syncthreads();

        float acc = 0.f;
        const float4* c2r = reinterpret_cast<const float4*>(&cbuf[i * PITCH]);
        const float4* xr  = reinterpret_cast<const float4*>(&xsm[k1sub * 64]);  // broadcast
#pragma unroll
        for (int q = 0; q < 16; q++) {
            float4 c  = c2r[q];   // conflict-free (pitch 68)
            float4 xv = xr[q];
            acc = fmaf(C1reg[4 * q + 0] * c.x, xv.x, acc);
            acc = fmaf(C1reg[4 * q + 1] * c.y, xv.y, acc);
            acc = fmaf(C1reg[4 * q + 2] * c.z, xv.z, acc);
            acc = fmaf(C1reg[4 * q + 3] * c.w, xv.w, acc);
        }
        out[(k1 * NH + k2) * MD + i] = acc;
    }
}

// ---------------------------------------------------------------------------
// Launch: inputs in metadata order: grid [193,193,64], M_weight [64,64], P [64,64]
// ---------------------------------------------------------------------------
extern "C" void kernel_launch(void* const* d_in, const int* in_sizes, int n_in,
                              void* d_out, int out_size) {
    const float* grid = (const float*)d_in[0];
    const float* Mw   = (const float*)d_in[1];
    const float* P    = (const float*)d_in[2];
    float* out        = (float*)d_out;

    build_cos_table<<<(NH * MD * MD + 255) / 256, 256>>>();
    compute_x<<<dim3(6, NH), 256>>>(grid, Mw);
    main_kernel<<<dim3(6, NH / 8), 512>>>(P, out);
}

// round 7
// speedup vs baseline: 1.4339x; 1.2971x over previous
#include <cuda_runtime.h>

#define NH 192            // nH = nW = 193 - 2 + 1
#define HG 193            // grid H/W
#define MD 64             // vec dim m
#define PITCH 68          // padded row (floats): conflict-free float4 LDS (68 % 32 == 4)

// Scratch (allocation-free rule: __device__ globals)
__device__ float g_cosT[NH * MD * MD];   // cos(2*pi*k / T[i,j]),  3 MB
__device__ float g_x[NH * NH * MD];      // x = win_avg(grid) @ M^T, 9.4 MB

// ---- packed f32x2 helpers (FFMA2/FMUL2 only reachable via PTX) -------------
__device__ __forceinline__ unsigned long long pk(float x, float y) {
    unsigned long long r;
    asm("mov.b64 %0, {%1, %2};" : "=l"(r) : "f"(x), "f"(y));
    return r;
}
__device__ __forceinline__ float2 upk(unsigned long long v) {
    float2 t;
    asm("mov.b64 {%0, %1}, %2;" : "=f"(t.x), "=f"(t.y) : "l"(v));
    return t;
}
__device__ __forceinline__ unsigned long long mul2(unsigned long long a,
                                                   unsigned long long b) {
    unsigned long long r;
    asm("mul.rn.f32x2 %0, %1, %2;" : "=l"(r) : "l"(a), "l"(b));
    return r;
}
__device__ __forceinline__ unsigned long long fma2(unsigned long long a,
                                                   unsigned long long b,
                                                   unsigned long long c) {
    unsigned long long r;
    asm("fma.rn.f32x2 %0, %1, %2, %3;" : "=l"(r) : "l"(a), "l"(b), "l"(c));
    return r;
}

// ---------------------------------------------------------------------------
// Fused prep kernel: CTAs [0, 3072) build the cos table; CTAs [3072, 4224)
// compute x = win_avg(grid) @ M^T (exact R2/R6 compute_x body — proven).
// Independent work; fusing overlaps the two phases in one launch.
// ---------------------------------------------------------------------------
__global__ void __launch_bounds__(256) fused_prep(const float* __restrict__ grid,
                                                  const float* __restrict__ Mw) {
    __shared__ float Msm[64][65];
    __shared__ __align__(16) float wv[4][64];

    int t = threadIdx.x;

    if (blockIdx.x < 3072) {
        // ---- cos table: cosT[k,i,j] = cosf(2*pi*k / (i*64 + j + 2)) ----
        int idx = blockIdx.x * 256 + t;
        int k = idx >> 12;
        int r = idx & 4095;
        int i = r >> 6;
        int j = r & 63;
        float period = (float)(i * MD + j + 2);
        float arg = 6.2831853071795864769f * (float)k / period;  // fp32, matches ref
        g_cosT[idx] = cosf(arg);
        return;
    }

    // ---- compute_x ----
    int bid = blockIdx.x - 3072;      // 0..1151
    int q  = t >> 6;
    int jl = t & 63;

    for (int e = t; e < 4096; e += 256) Msm[e >> 6][e & 63] = Mw[e];
    __syncthreads();
    float Mreg[64];
#pragma unroll
    for (int l = 0; l < 64; l++) Mreg[l] = Msm[jl][l];

    int k1     = bid / 6;
    int k2base = (bid % 6) * 32;

    for (int g = 0; g < 8; g++) {
        __syncthreads();  // protect wv reuse
        int k2 = k2base + g * 4 + q;
        const float* g00 = grid + ((k1 * HG + k2) * MD);
        wv[q][jl] = 0.25f * (g00[jl] + g00[MD + jl] +
                             g00[HG * MD + jl] + g00[HG * MD + MD + jl]);
        __syncthreads();

        float acc = 0.f;
        const float4* wv4 = reinterpret_cast<const float4*>(&wv[q][0]);
#pragma unroll
        for (int l4 = 0; l4 < 16; l4++) {
            float4 w = wv4[l4];
            acc = fmaf(Mreg[4 * l4 + 0], w.x, acc);
            acc = fmaf(Mreg[4 * l4 + 1], w.y, acc);
            acc = fmaf(Mreg[4 * l4 + 2], w.z, acc);
            acc = fmaf(Mreg[4 * l4 + 3], w.w, acc);
        }
        g_x[(k1 * NH + k2) * MD + jl] = acc;
    }
}

// ---------------------------------------------------------------------------
// Kernel 3: Nk[b,i] = sum_j x[b,j] * (P[i,j]*cosT[k1,i,j]) * cosT[k2,i,j]
//
// R6 skeleton (PASSING): 512 threads = (k1sub 0..7) x (i 0..63), ONE output
// per thread per k2; grid (6 k2-chunks of 32, 24 k1-tiles of 8) = 144 CTAs.
// Round-7 deltas (both exonerated by R3/R4/R5 error forensics):
//   + register prefetch of next cos slice / x element (hides LDG latency)
//   + f32x2 packed inner loop (halves FMA-pipe instruction count)
// ---------------------------------------------------------------------------
__global__ void __launch_bounds__(512, 1) main_kernel(const float* __restrict__ P,
                                                      float* __restrict__ out) {
    __shared__ __align__(16) float cbuf[64 * PITCH];   // 17.4 KB cos slice (swing buffer)
    __shared__ float Ps[64][65];
    __shared__ __align__(16) float xsm[8 * 64];        // 8 x rows for current k2

    int t      = threadIdx.x;
    int i      = t & 63;
    int k1sub  = t >> 6;                // 0..7
    int k1base = blockIdx.y * 8;
    int k1     = k1base + k1sub;

    // stage P once (coalesced)
    for (int e = t; e < 4096; e += 512) Ps[e >> 6][e & 63] = P[e];

    // --- build C1p: stage each of the 8 k1 cos slices (pipelined LDG); the
    //     owning eighth packs C1p[q] = (P*cos1)[i, 2q..2q+1] into f32x2 regs ---
    unsigned long long C1p[32];
    float4 bpre0, bpre1;
    {
        const float4* s0 = reinterpret_cast<const float4*>(g_cosT + k1base * 4096);
        bpre0 = s0[t];
        bpre1 = s0[t + 512];
    }
    for (int s = 0; s < 8; s++) {
        __syncthreads();                  // cbuf free (prev round's readers done)
        {
            int e0 = t * 4;
            int e1 = (t + 512) * 4;
            *reinterpret_cast<float4*>(&cbuf[(e0 >> 6) * PITCH + (e0 & 63)]) = bpre0;
            *reinterpret_cast<float4*>(&cbuf[(e1 >> 6) * PITCH + (e1 & 63)]) = bpre1;
        }
        __syncthreads();
        if (s + 1 < 8) {                  // prefetch next slice during read phase
            const float4* sn = reinterpret_cast<const float4*>(
                g_cosT + (k1base + s + 1) * 4096);
            bpre0 = sn[t];
            bpre1 = sn[t + 512];
        }
        if (k1sub == s) {
#pragma unroll
            for (int q = 0; q < 32; q++)
                C1p[q] = pk(cbuf[i * PITCH + 2 * q]     * Ps[i][2 * q],
                            cbuf[i * PITCH + 2 * q + 1] * Ps[i][2 * q + 1]);
        }
    }

    int k2base = blockIdx.x * 32;
    int xrow   = t >> 6;                 // 0..7
    int xcol   = t & 63;

    // --- prefetch iter 0 (registers; no smem conflict with build readers) ---
    float4 pre0, pre1;
    float  xpre;
    {
        const float4* src = reinterpret_cast<const float4*>(g_cosT + k2base * 4096);
        pre0 = src[t];
        pre1 = src[t + 512];
        xpre = g_x[((k1base + xrow) * NH + k2base) * MD + xcol];
    }

    for (int kk = 0; kk < 32; kk++) {
        __syncthreads();   // readers of previous slice (or C1 build) are done

        // STS prefetched slice + x rows (R6's proven two-barrier pattern)
        {
            int e0 = t * 4;
            int e1 = (t + 512) * 4;
            *reinterpret_cast<float4*>(&cbuf[(e0 >> 6) * PITCH + (e0 & 63)]) = pre0;
            *reinterpret_cast<float4*>(&cbuf[(e1 >> 6) * PITCH + (e1 & 63)]) = pre1;
        }
        xsm[xrow * 64 + xcol] = xpre;
        __syncthreads();

        // issue next iteration's LDGs (latency hidden under compute below)
        if (kk + 1 < 32) {
            int k2n = k2base + kk + 1;
            const float4* src = reinterpret_cast<const float4*>(g_cosT + k2n * 4096);
            pre0 = src[t];
            pre1 = src[t + 512];
            xpre = g_x[((k1base + xrow) * NH + k2n) * MD + xcol];
        }

        const ulonglong2* c2r = reinterpret_cast<const ulonglong2*>(&cbuf[i * PITCH]);
        const ulonglong2* xr  = reinterpret_cast<const ulonglong2*>(&xsm[k1sub * 64]);

        unsigned long long a0 = 0ULL, a1 = 0ULL;
#pragma unroll
        for (int q = 0; q < 16; q++) {
            ulonglong2 c  = c2r[q];   // conflict-free (pitch 68)
            ulonglong2 xv = xr[q];    // broadcast
            a0 = fma2(mul2(C1p[2 * q],     c.x), xv.x, a0);
            a1 = fma2(mul2(C1p[2 * q + 1], c.y), xv.y, a1);
        }

        int k2 = k2base + kk;
        float2 f0 = upk(a0), f1 = upk(a1);
        out[(k1 * NH + k2) * MD + i] = (f0.x + f0.y) + (f1.x + f1.y);
    }
}

// ---------------------------------------------------------------------------
// Launch: inputs in metadata order: grid [193,193,64], M_weight [64,64], P [64,64]
// ---------------------------------------------------------------------------
extern "C" void kernel_launch(void* const* d_in, const int* in_sizes, int n_in,
                              void* d_out, int out_size) {
    const float* grid = (const float*)d_in[0];
    const float* Mw   = (const float*)d_in[1];
    const float* P    = (const float*)d_in[2];
    float* out        = (float*)d_out;

    fused_prep<<<3072 + 1152, 256>>>(grid, Mw);
    main_kernel<<<dim3(6, NH / 8), 512>>>(P, out);
}